// round 3
// baseline (speedup 1.0000x reference)
#include <cuda_runtime.h>
#include <cstdint>
#include <math.h>

// Problem dims (fixed for this problem)
#define NTOK 4096          // B*T
#define DDIM 1024
#define NEXP 16
#define HDIM 1536
#define RTOT (2*NTOK)      // total routed rows (top-2)

// GEMM tiling
#define BM 128
#define BN 128
#define BK 16
#define SSTR 20            // padded smem row stride (conflict-free for frag loads)

// ---------------- device scratch (static allocation allowed) ----------------
__device__ float g_h[(size_t)RTOT * HDIM];    // expert hidden activations
__device__ float g_y[(size_t)RTOT * DDIM];    // expert outputs
__device__ int   g_perm[RTOT];                // slot -> token
__device__ int   g_slot[RTOT];                // (token,k) -> slot
__device__ float g_gate[RTOT];                // (token,k) -> gate
__device__ int   g_eid[RTOT];                 // (token,k) -> expert
__device__ int   g_cnt[NEXP];
__device__ int   g_off[NEXP];
__device__ int   g_cur[NEXP];

// ---------------- helpers ----------------
__device__ __forceinline__ uint32_t f2tf(float f) {
    uint32_t r; asm("cvt.rna.tf32.f32 %0, %1;" : "=r"(r) : "f"(f)); return r;
}
__device__ __forceinline__ void mma_tf32(float* c, const uint32_t* a, const uint32_t* b) {
    asm volatile("mma.sync.aligned.m16n8k8.row.col.f32.tf32.tf32.f32 "
        "{%0,%1,%2,%3}, {%4,%5,%6,%7}, {%8,%9}, {%0,%1,%2,%3};"
        : "+f"(c[0]), "+f"(c[1]), "+f"(c[2]), "+f"(c[3])
        : "r"(a[0]), "r"(a[1]), "r"(a[2]), "r"(a[3]), "r"(b[0]), "r"(b[1]));
}
__device__ __forceinline__ float gelu_tanh(float v) {
    float u = 0.7978845608028654f * (v + 0.044715f * v * v * v);
    return 0.5f * v * (1.0f + tanhf(u));
}

// ---------------- router: one warp per token ----------------
__global__ void router_kernel(const float* __restrict__ x,
                              const float* __restrict__ rw) {
    int warp = (blockIdx.x * blockDim.x + threadIdx.x) >> 5;
    int lane = threadIdx.x & 31;
    if (warp >= NTOK) return;
    const float4* xr = (const float4*)(x + (size_t)warp * DDIM);

    float best1 = -INFINITY, best2 = -INFINITY;
    int i1 = 0, i2 = 0;
    for (int e = 0; e < NEXP; e++) {
        const float4* wr = (const float4*)(rw + (size_t)e * DDIM);
        float s = 0.f;
        #pragma unroll 4
        for (int d = lane; d < DDIM / 4; d += 32) {
            float4 a = xr[d], b = wr[d];
            s += a.x * b.x + a.y * b.y + a.z * b.z + a.w * b.w;
        }
        #pragma unroll
        for (int o = 16; o > 0; o >>= 1) s += __shfl_xor_sync(0xffffffffu, s, o);
        if (s > best1)      { best2 = best1; i2 = i1; best1 = s; i1 = e; }
        else if (s > best2) { best2 = s; i2 = e; }
    }
    if (lane == 0) {
        float t = expf(best2 - best1);     // <= 1
        float denom = 1.0f + t;
        g_eid[2 * warp]     = i1;  g_gate[2 * warp]     = 1.0f / denom;
        g_eid[2 * warp + 1] = i2;  g_gate[2 * warp + 1] = t / denom;
    }
}

// ---------------- count + scan + aux loss (deterministic), 512 threads ----------------
__global__ void scan_kernel(float* __restrict__ out_tail, int tail_count) {
    __shared__ int   cnt_s[NEXP];
    __shared__ float gs_s[NEXP];
    int w = threadIdx.x >> 5, lane = threadIdx.x & 31;
    if (w < NEXP) {
        int c = 0; float gs = 0.f;
        for (int i = lane; i < RTOT; i += 32) {
            if (g_eid[i] == w) { c++; gs += g_gate[i]; }
        }
        #pragma unroll
        for (int o = 16; o > 0; o >>= 1) {
            c  += __shfl_xor_sync(0xffffffffu, c, o);
            gs += __shfl_xor_sync(0xffffffffu, gs, o);
        }
        if (lane == 0) { cnt_s[w] = c; gs_s[w] = gs; }
    }
    __syncthreads();
    if (threadIdx.x == 0) {
        int run = 0; float aux = 0.f;
        for (int e = 0; e < NEXP; e++) {
            g_cnt[e] = cnt_s[e]; g_off[e] = run; g_cur[e] = run; run += cnt_s[e];
            float f = (float)cnt_s[e] / (float)RTOT;
            float m = gs_s[e] / fmaxf((float)cnt_s[e], 1.0f);
            aux += f * m;
        }
        aux = 0.02f * aux / (float)NEXP;
        for (int i = 0; i < tail_count; i++) out_tail[i] = aux;
    }
}

// ---------------- scatter tokens into per-expert groups ----------------
__global__ void scatter_kernel() {
    int i = blockIdx.x * blockDim.x + threadIdx.x;
    if (i >= RTOT) return;
    int e = g_eid[i];
    int pos = atomicAdd(&g_cur[e], 1);
    g_perm[pos] = i >> 1;       // token index
    g_slot[i] = pos;
}

// ---------------- grouped TF32 GEMM ----------------
// GATHER=true : A rows gathered from Aparam (x) via g_perm; C = g_h, GELU+b1
// GATHER=false: A rows from g_h (contiguous); C = g_y, +b2
// Out-of-range rows (tile tail past cnt) are CLAMPED to a valid row: their
// loads read valid memory, their results are garbage, and the epilogue's
// row < cnt guard never stores them.
template<int KDIM, bool GATHER, bool DOGELU>
__global__ __launch_bounds__(256, 2)
void moe_gemm_kernel(const float* __restrict__ Aparam,
                     const float* __restrict__ Wbase,   // [E, NTOT, KDIM]
                     const float* __restrict__ Bias,    // [E, NTOT]
                     int NTOT) {
    __shared__ __align__(16) float As[2][BM][SSTR];
    __shared__ __align__(16) float Bs[2][BN][SSTR];
    __shared__ const float* aptr[BM];

    const int e = blockIdx.y;
    const int cnt = g_cnt[e];
    const int m0 = blockIdx.x * BM;
    if (m0 >= cnt) return;
    const int off = g_off[e];
    const int n0 = blockIdx.z * BN;
    const int tid = threadIdx.x;

    const float* Asrc = GATHER ? Aparam : g_h;
    float* Cbase = DOGELU ? g_h : g_y;

    for (int r = tid; r < BM; r += 256) {
        int mi = m0 + r;
        if (mi >= cnt) mi = cnt - 1;              // clamp: always a valid row
        int row = GATHER ? g_perm[off + mi] : (off + mi);
        aptr[r] = Asrc + (size_t)row * KDIM;
    }
    __syncthreads();

    const float* Wp = Wbase + ((size_t)e * NTOT + n0) * KDIM;
    uint32_t sA = (uint32_t)__cvta_generic_to_shared(&As[0][0][0]);
    uint32_t sB = (uint32_t)__cvta_generic_to_shared(&Bs[0][0][0]);

    const int warp = tid >> 5, lane = tid & 31;
    const int wm = (warp & 1) * 64;
    const int wn = (warp >> 1) * 32;
    const int gid = lane >> 2, tig = lane & 3;

    float acc[4][4][4];
    #pragma unroll
    for (int a = 0; a < 4; a++)
        #pragma unroll
        for (int b = 0; b < 4; b++)
            #pragma unroll
            for (int c = 0; c < 4; c++) acc[a][b][c] = 0.f;

    auto load_stage = [&](int st, int k0) {
        #pragma unroll
        for (int i = 0; i < 2; i++) {
            int idx = tid + i * 256;          // 0..511
            int r = idx >> 2;                 // 0..127
            int c = (idx & 3) << 2;           // 0,4,8,12
            const float* src = aptr[r] + k0 + c;
            uint32_t dst = sA + (((st * BM + r) * SSTR + c) << 2);
            asm volatile("cp.async.cg.shared.global [%0], [%1], 16;"
                         :: "r"(dst), "l"(src));
        }
        #pragma unroll
        for (int i = 0; i < 2; i++) {
            int idx = tid + i * 256;
            int r = idx >> 2;
            int c = (idx & 3) << 2;
            const float* src = Wp + (size_t)r * KDIM + k0 + c;
            uint32_t dst = sB + (((st * BN + r) * SSTR + c) << 2);
            asm volatile("cp.async.cg.shared.global [%0], [%1], 16;"
                         :: "r"(dst), "l"(src));
        }
        asm volatile("cp.async.commit_group;");
    };

    const int KT = KDIM / BK;
    load_stage(0, 0);

    #pragma unroll 1
    for (int kt = 0; kt < KT; kt++) {
        if (kt + 1 < KT) {
            load_stage((kt + 1) & 1, (kt + 1) * BK);
            asm volatile("cp.async.wait_group 1;");
        } else {
            asm volatile("cp.async.wait_group 0;");
        }
        __syncthreads();

        const float (*A)[SSTR] = As[kt & 1];
        const float (*B)[SSTR] = Bs[kt & 1];

        #pragma unroll
        for (int kk = 0; kk < BK; kk += 8) {
            uint32_t af[4][4], bf[4][2];
            #pragma unroll
            for (int im = 0; im < 4; im++) {
                int r = wm + im * 16 + gid;
                int c = kk + tig;
                af[im][0] = f2tf(A[r][c]);
                af[im][1] = f2tf(A[r + 8][c]);
                af[im][2] = f2tf(A[r][c + 4]);
                af[im][3] = f2tf(A[r + 8][c + 4]);
            }
            #pragma unroll
            for (int in = 0; in < 4; in++) {
                int cN = wn + in * 8 + gid;
                bf[in][0] = f2tf(B[cN][kk + tig]);
                bf[in][1] = f2tf(B[cN][kk + tig + 4]);
            }
            #pragma unroll
            for (int im = 0; im < 4; im++)
                #pragma unroll
                for (int in = 0; in < 4; in++)
                    mma_tf32(acc[im][in], af[im], bf[in]);
        }
        __syncthreads();
    }

    // epilogue
    const float* bias_e = Bias + (size_t)e * NTOT;
    #pragma unroll
    for (int im = 0; im < 4; im++) {
        int r0 = m0 + wm + im * 16 + gid;
        #pragma unroll
        for (int in = 0; in < 4; in++) {
            int col = n0 + wn + in * 8 + 2 * tig;
            float bv0 = bias_e[col], bv1 = bias_e[col + 1];
            if (r0 < cnt) {
                float v0 = acc[im][in][0] + bv0;
                float v1 = acc[im][in][1] + bv1;
                if (DOGELU) { v0 = gelu_tanh(v0); v1 = gelu_tanh(v1); }
                size_t base = (size_t)(off + r0) * NTOT + col;
                Cbase[base] = v0; Cbase[base + 1] = v1;
            }
            if (r0 + 8 < cnt) {
                float v2 = acc[im][in][2] + bv0;
                float v3 = acc[im][in][3] + bv1;
                if (DOGELU) { v2 = gelu_tanh(v2); v3 = gelu_tanh(v3); }
                size_t base = (size_t)(off + r0 + 8) * NTOT + col;
                Cbase[base] = v2; Cbase[base + 1] = v3;
            }
        }
    }
}

// ---------------- combine: out[n] = g0*y[slot0] + g1*y[slot1] ----------------
__global__ void combine_kernel(float* __restrict__ out) {
    int n = blockIdx.x;                     // token
    int c = threadIdx.x << 2;               // 256 threads * 4 floats = 1024
    float g0 = g_gate[2 * n], g1 = g_gate[2 * n + 1];
    int s0 = g_slot[2 * n], s1 = g_slot[2 * n + 1];
    float4 y0 = *(const float4*)(g_y + (size_t)s0 * DDIM + c);
    float4 y1 = *(const float4*)(g_y + (size_t)s1 * DDIM + c);
    float4 o;
    o.x = g0 * y0.x + g1 * y1.x;
    o.y = g0 * y0.y + g1 * y1.y;
    o.z = g0 * y0.z + g1 * y1.z;
    o.w = g0 * y0.w + g1 * y1.w;
    *(float4*)(out + (size_t)n * DDIM + c) = o;
}

// ---------------- launch ----------------
extern "C" void kernel_launch(void* const* d_in, const int* in_sizes, int n_in,
                              void* d_out, int out_size) {
    const float* x  = (const float*)d_in[0];
    const float* rw = (const float*)d_in[1];
    const float* w1 = (const float*)d_in[2];
    const float* b1 = (const float*)d_in[3];
    const float* w2 = (const float*)d_in[4];
    const float* b2 = (const float*)d_in[5];
    float* out = (float*)d_out;

    router_kernel<<<(NTOK * 32 + 255) / 256, 256>>>(x, rw);

    int tail = out_size - NTOK * DDIM;
    if (tail < 0) tail = 0;
    scan_kernel<<<1, 512>>>(out + (size_t)NTOK * DDIM, tail);

    scatter_kernel<<<(RTOT + 255) / 256, 256>>>();

    dim3 g1(32, NEXP, HDIM / BN);   // (tiles_m, experts, tiles_n)
    moe_gemm_kernel<DDIM, true, true><<<g1, 256>>>(x, w1, b1, HDIM);

    dim3 g2(32, NEXP, DDIM / BN);
    moe_gemm_kernel<HDIM, false, false><<<g2, 256>>>(nullptr, w2, b2, DDIM);

    combine_kernel<<<NTOK, 256>>>(out);
}